// round 1
// baseline (speedup 1.0000x reference)
#include <cuda_runtime.h>
#include <math.h>

// ---------------------------------------------------------------------------
// Problem constants
// ---------------------------------------------------------------------------
#define E_DIM   1024
#define H_NUM   16
#define HD_DIM  64
#define F_DIM   4096
#define B_NUM   4
#define S_LEN   2048
#define N_TOK   (B_NUM * S_LEN)      // 8192
#define BH_NUM  (B_NUM * H_NUM)      // 64
#define LN_EPS  1e-5f

// ---------------------------------------------------------------------------
// Scratch (static device globals; allocation inside kernel_launch is banned)
// ---------------------------------------------------------------------------
__device__ float g_Q   [(size_t)N_TOK * E_DIM];                 // 32 MB
__device__ float g_K   [(size_t)N_TOK * E_DIM];                 // 32 MB
__device__ float g_V   [(size_t)N_TOK * E_DIM];                 // 32 MB
__device__ float g_P   [(size_t)BH_NUM * S_LEN * S_LEN];        // 1 GB (scores/probs)
__device__ float g_attn[(size_t)N_TOK * E_DIM];                 // 32 MB
__device__ float g_res1[(size_t)N_TOK * E_DIM];                 // 32 MB
__device__ float g_h   [(size_t)N_TOK * E_DIM];                 // 32 MB
__device__ float g_ffn [(size_t)N_TOK * F_DIM];                 // 128 MB
__device__ float g_res2[(size_t)N_TOK * E_DIM];                 // 32 MB

// ---------------------------------------------------------------------------
// Block reductions (256 threads = 8 warps)
// ---------------------------------------------------------------------------
__device__ __forceinline__ float blockReduceSum256(float v) {
    __shared__ float s[8];
    int lane = threadIdx.x & 31, wid = threadIdx.x >> 5;
    #pragma unroll
    for (int o = 16; o; o >>= 1) v += __shfl_xor_sync(0xffffffffu, v, o);
    __syncthreads();
    if (lane == 0) s[wid] = v;
    __syncthreads();
    float r = s[0];
    #pragma unroll
    for (int i = 1; i < 8; i++) r += s[i];
    return r;
}

__device__ __forceinline__ float blockReduceMax256(float v) {
    __shared__ float s[8];
    int lane = threadIdx.x & 31, wid = threadIdx.x >> 5;
    #pragma unroll
    for (int o = 16; o; o >>= 1) v = fmaxf(v, __shfl_xor_sync(0xffffffffu, v, o));
    __syncthreads();
    if (lane == 0) s[wid] = v;
    __syncthreads();
    float r = s[0];
    #pragma unroll
    for (int i = 1; i < 8; i++) r = fmaxf(r, s[i]);
    return r;
}

// ---------------------------------------------------------------------------
// Generic NT SGEMM:  C[M,N] = alpha * A[M,K] @ B[N,K]^T  (+bias +relu +residual)
// Batched over z (grid.z): per-z offsets A += zb*aOffB + zh*aOffH (zb=z/nH,
// zh=z%nH), same for B; C/residual advance by z*cStrideZ.
// Tile: 128x128x16, 256 threads, 8x8 micro-tile.
// Requires: M%128==0, N%128==0, K%16==0, 16B-aligned rows.
// ---------------------------------------------------------------------------
__global__ __launch_bounds__(256) void sgemm_nt(
    const float* __restrict__ A, int lda, long aOffB, long aOffH,
    const float* __restrict__ B, int ldb, long bOffB, long bOffH,
    float* __restrict__ C, int ldc, long cStrideZ,
    const float* __restrict__ residual,   // same layout as C, or null
    const float* __restrict__ bias,       // length N, or null
    int M, int N, int K, int nH,
    float alpha, int relu)
{
    const int BM = 128, BN = 128, BK = 16;
    int z  = blockIdx.z;
    int zb = z / nH, zh = z % nH;
    const float* Az = A + (long)zb * aOffB + (long)zh * aOffH;
    const float* Bz = B + (long)zb * bOffB + (long)zh * bOffH;
    float*       Cz = C + (long)z * cStrideZ;
    const float* Rz = residual ? residual + (long)z * cStrideZ : nullptr;

    __shared__ float As[BK][BM];
    __shared__ float Bs[BK][BN];

    int tid = threadIdx.x;
    int tx = tid & 15, ty = tid >> 4;
    int row0 = blockIdx.y * BM;
    int col0 = blockIdx.x * BN;

    float acc[8][8];
    #pragma unroll
    for (int i = 0; i < 8; i++)
        #pragma unroll
        for (int j = 0; j < 8; j++) acc[i][j] = 0.f;

    for (int k0 = 0; k0 < K; k0 += BK) {
        // Load A tile (128x16) and B tile (128x16), transposed into smem.
        #pragma unroll
        for (int l = 0; l < 2; l++) {
            int j  = tid + l * 256;        // 0..511 float4 slots
            int r  = j >> 2;               // 0..127
            int c4 = (j & 3) * 4;          // 0,4,8,12
            float4 a = *reinterpret_cast<const float4*>(
                &Az[(long)(row0 + r) * lda + k0 + c4]);
            As[c4 + 0][r] = a.x; As[c4 + 1][r] = a.y;
            As[c4 + 2][r] = a.z; As[c4 + 3][r] = a.w;
            float4 b = *reinterpret_cast<const float4*>(
                &Bz[(long)(col0 + r) * ldb + k0 + c4]);
            Bs[c4 + 0][r] = b.x; Bs[c4 + 1][r] = b.y;
            Bs[c4 + 2][r] = b.z; Bs[c4 + 3][r] = b.w;
        }
        __syncthreads();

        #pragma unroll
        for (int kk = 0; kk < BK; kk++) {
            float a[8], b[8];
            *reinterpret_cast<float4*>(&a[0]) =
                *reinterpret_cast<const float4*>(&As[kk][ty * 8]);
            *reinterpret_cast<float4*>(&a[4]) =
                *reinterpret_cast<const float4*>(&As[kk][ty * 8 + 4]);
            *reinterpret_cast<float4*>(&b[0]) =
                *reinterpret_cast<const float4*>(&Bs[kk][tx * 8]);
            *reinterpret_cast<float4*>(&b[4]) =
                *reinterpret_cast<const float4*>(&Bs[kk][tx * 8 + 4]);
            #pragma unroll
            for (int i = 0; i < 8; i++)
                #pragma unroll
                for (int j = 0; j < 8; j++)
                    acc[i][j] += a[i] * b[j];
        }
        __syncthreads();
    }

    // Epilogue (vectorized float4 stores)
    #pragma unroll
    for (int i = 0; i < 8; i++) {
        long r = row0 + ty * 8 + i;
        float*       crow = &Cz[r * (long)ldc + col0 + tx * 8];
        const float* rrow = Rz ? &Rz[r * (long)ldc + col0 + tx * 8] : nullptr;
        #pragma unroll
        for (int jj = 0; jj < 2; jj++) {
            float4 o;
            o.x = acc[i][jj * 4 + 0] * alpha;
            o.y = acc[i][jj * 4 + 1] * alpha;
            o.z = acc[i][jj * 4 + 2] * alpha;
            o.w = acc[i][jj * 4 + 3] * alpha;
            if (bias) {
                float4 bv = *reinterpret_cast<const float4*>(
                    &bias[col0 + tx * 8 + jj * 4]);
                o.x += bv.x; o.y += bv.y; o.z += bv.z; o.w += bv.w;
            }
            if (relu) {
                o.x = fmaxf(o.x, 0.f); o.y = fmaxf(o.y, 0.f);
                o.z = fmaxf(o.z, 0.f); o.w = fmaxf(o.w, 0.f);
            }
            if (rrow) {
                float4 rv = *reinterpret_cast<const float4*>(&rrow[jj * 4]);
                o.x += rv.x; o.y += rv.y; o.z += rv.z; o.w += rv.w;
            }
            *reinterpret_cast<float4*>(&crow[jj * 4]) = o;
        }
    }
}

// ---------------------------------------------------------------------------
// PV GEMM (NN): for each (b,h): C[s,d] = sum_k P[s,k] * V[k,d], d<64.
// Writes directly into attn buffer laid out [b, s, (h,hd)].
// Tile: 128x64x16, 256 threads, 8x4 micro-tile.
// ---------------------------------------------------------------------------
__global__ __launch_bounds__(256) void sgemm_nn_pv(
    const float* __restrict__ P,    // [BH, S, S]
    const float* __restrict__ V,    // [N_TOK, E] = [b, s, (h,hd)]
    float* __restrict__ Cattn)      // [N_TOK, E]
{
    const int BM = 128, BK = 16;
    int z  = blockIdx.z;
    int zb = z >> 4, zh = z & 15;
    const float* Az = P + (size_t)z * S_LEN * S_LEN;
    const float* Bz = V + (size_t)zb * S_LEN * E_DIM + zh * HD_DIM;
    float*       Cz = Cattn + (size_t)zb * S_LEN * E_DIM + zh * HD_DIM;

    __shared__ float As[BK][BM];
    __shared__ float Bs[BK][64];

    int tid = threadIdx.x;
    int tx = tid & 15, ty = tid >> 4;
    int row0 = blockIdx.y * BM;

    float acc[8][4];
    #pragma unroll
    for (int i = 0; i < 8; i++)
        #pragma unroll
        for (int j = 0; j < 4; j++) acc[i][j] = 0.f;

    for (int k0 = 0; k0 < S_LEN; k0 += BK) {
        #pragma unroll
        for (int l = 0; l < 2; l++) {
            int j  = tid + l * 256;
            int r  = j >> 2;
            int c4 = (j & 3) * 4;
            float4 a = *reinterpret_cast<const float4*>(
                &Az[(size_t)(row0 + r) * S_LEN + k0 + c4]);
            As[c4 + 0][r] = a.x; As[c4 + 1][r] = a.y;
            As[c4 + 2][r] = a.z; As[c4 + 3][r] = a.w;
        }
        {
            int r  = tid >> 4;          // 0..15 (k row)
            int c4 = (tid & 15) * 4;    // 0..60 (d col)
            float4 b = *reinterpret_cast<const float4*>(
                &Bz[(size_t)(k0 + r) * E_DIM + c4]);
            *reinterpret_cast<float4*>(&Bs[r][c4]) = b;
        }
        __syncthreads();

        #pragma unroll
        for (int kk = 0; kk < BK; kk++) {
            float a[8], b[4];
            *reinterpret_cast<float4*>(&a[0]) =
                *reinterpret_cast<const float4*>(&As[kk][ty * 8]);
            *reinterpret_cast<float4*>(&a[4]) =
                *reinterpret_cast<const float4*>(&As[kk][ty * 8 + 4]);
            *reinterpret_cast<float4*>(&b[0]) =
                *reinterpret_cast<const float4*>(&Bs[kk][tx * 4]);
            #pragma unroll
            for (int i = 0; i < 8; i++)
                #pragma unroll
                for (int j = 0; j < 4; j++)
                    acc[i][j] += a[i] * b[j];
        }
        __syncthreads();
    }

    #pragma unroll
    for (int i = 0; i < 8; i++) {
        size_t r = row0 + ty * 8 + i;
        float4 o = make_float4(acc[i][0], acc[i][1], acc[i][2], acc[i][3]);
        *reinterpret_cast<float4*>(&Cz[r * E_DIM + tx * 4]) = o;
    }
}

// ---------------------------------------------------------------------------
// Row softmax over S_LEN=2048, in place. One block (256 thr) per row.
// ---------------------------------------------------------------------------
__global__ __launch_bounds__(256) void softmax_rows(float* __restrict__ P) {
    size_t row = blockIdx.x;
    float4* p4 = reinterpret_cast<float4*>(P + row * (size_t)S_LEN);
    int tid = threadIdx.x;

    float4 v0 = p4[tid];
    float4 v1 = p4[tid + 256];

    float m = fmaxf(fmaxf(fmaxf(v0.x, v0.y), fmaxf(v0.z, v0.w)),
                    fmaxf(fmaxf(v1.x, v1.y), fmaxf(v1.z, v1.w)));
    m = blockReduceMax256(m);

    v0.x = __expf(v0.x - m); v0.y = __expf(v0.y - m);
    v0.z = __expf(v0.z - m); v0.w = __expf(v0.w - m);
    v1.x = __expf(v1.x - m); v1.y = __expf(v1.y - m);
    v1.z = __expf(v1.z - m); v1.w = __expf(v1.w - m);

    float s = (v0.x + v0.y + v0.z + v0.w) + (v1.x + v1.y + v1.z + v1.w);
    s = blockReduceSum256(s);
    float inv = 1.f / s;

    v0.x *= inv; v0.y *= inv; v0.z *= inv; v0.w *= inv;
    v1.x *= inv; v1.y *= inv; v1.z *= inv; v1.w *= inv;
    p4[tid]       = v0;
    p4[tid + 256] = v1;
}

// ---------------------------------------------------------------------------
// LayerNorm over E=1024. One block (256 thr) per row, 1 float4/thread.
// ---------------------------------------------------------------------------
__global__ __launch_bounds__(256) void layernorm_rows(
    const float* __restrict__ in,
    const float* __restrict__ g, const float* __restrict__ b,
    float* __restrict__ out)
{
    size_t row = blockIdx.x;
    const float4* x4 = reinterpret_cast<const float4*>(in + row * E_DIM);
    float4 v = x4[threadIdx.x];

    float s  = v.x + v.y + v.z + v.w;
    float ss = v.x * v.x + v.y * v.y + v.z * v.z + v.w * v.w;
    s  = blockReduceSum256(s);
    ss = blockReduceSum256(ss);

    const float invE = 1.f / (float)E_DIM;
    float mu   = s * invE;
    float var  = ss * invE - mu * mu;
    float rstd = rsqrtf(var + LN_EPS);

    float4 gv = reinterpret_cast<const float4*>(g)[threadIdx.x];
    float4 bv = reinterpret_cast<const float4*>(b)[threadIdx.x];
    float4 o;
    o.x = (v.x - mu) * rstd * gv.x + bv.x;
    o.y = (v.y - mu) * rstd * gv.y + bv.y;
    o.z = (v.z - mu) * rstd * gv.z + bv.z;
    o.w = (v.w - mu) * rstd * gv.w + bv.w;
    reinterpret_cast<float4*>(out + row * E_DIM)[threadIdx.x] = o;
}

// ---------------------------------------------------------------------------
// Launch: full transformer block
// Inputs (metadata order): 0:x 1:Wq 2:Wk 3:Wv 4:Wo 5:g1 6:b1 7:g2 8:b2
//                          9:W1 10:bb1 11:W2 12:bb2
// ---------------------------------------------------------------------------
extern "C" void kernel_launch(void* const* d_in, const int* in_sizes, int n_in,
                              void* d_out, int out_size)
{
    const float* x   = (const float*)d_in[0];
    const float* Wq  = (const float*)d_in[1];
    const float* Wk  = (const float*)d_in[2];
    const float* Wv  = (const float*)d_in[3];
    const float* Wo  = (const float*)d_in[4];
    const float* g1  = (const float*)d_in[5];
    const float* b1  = (const float*)d_in[6];
    const float* g2  = (const float*)d_in[7];
    const float* b2  = (const float*)d_in[8];
    const float* W1  = (const float*)d_in[9];
    const float* bb1 = (const float*)d_in[10];
    const float* W2  = (const float*)d_in[11];
    const float* bb2 = (const float*)d_in[12];
    float* out = (float*)d_out;

    float *Q, *K, *V, *P, *attn, *res1, *h, *ffn, *res2;
    cudaGetSymbolAddress((void**)&Q,    g_Q);
    cudaGetSymbolAddress((void**)&K,    g_K);
    cudaGetSymbolAddress((void**)&V,    g_V);
    cudaGetSymbolAddress((void**)&P,    g_P);
    cudaGetSymbolAddress((void**)&attn, g_attn);
    cudaGetSymbolAddress((void**)&res1, g_res1);
    cudaGetSymbolAddress((void**)&h,    g_h);
    cudaGetSymbolAddress((void**)&ffn,  g_ffn);
    cudaGetSymbolAddress((void**)&res2, g_res2);

    dim3 blk(256);

    // --- QKV projections: [8192,1024] @ [1024,1024]^T ---
    dim3 gp(E_DIM / 128, N_TOK / 128, 1);
    sgemm_nt<<<gp, blk>>>(x, E_DIM, 0, 0, Wq, E_DIM, 0, 0, Q, E_DIM, 0,
                          nullptr, nullptr, N_TOK, E_DIM, E_DIM, 1, 1.f, 0);
    sgemm_nt<<<gp, blk>>>(x, E_DIM, 0, 0, Wk, E_DIM, 0, 0, K, E_DIM, 0,
                          nullptr, nullptr, N_TOK, E_DIM, E_DIM, 1, 1.f, 0);
    sgemm_nt<<<gp, blk>>>(x, E_DIM, 0, 0, Wv, E_DIM, 0, 0, V, E_DIM, 0,
                          nullptr, nullptr, N_TOK, E_DIM, E_DIM, 1, 1.f, 0);

    // --- scores = 1/sqrt(hd) * Q_bh @ K_bh^T, batched over 64 (b,h) pairs ---
    dim3 gs(S_LEN / 128, S_LEN / 128, BH_NUM);
    sgemm_nt<<<gs, blk>>>(Q, E_DIM, (long)S_LEN * E_DIM, HD_DIM,
                          K, E_DIM, (long)S_LEN * E_DIM, HD_DIM,
                          P, S_LEN, (long)S_LEN * S_LEN,
                          nullptr, nullptr, S_LEN, S_LEN, HD_DIM, H_NUM,
                          0.125f, 0);

    // --- softmax rows ---
    softmax_rows<<<BH_NUM * S_LEN, 256>>>(P);

    // --- attn = P @ V_bh, written into [b,s,(h,hd)] layout ---
    dim3 gpv(1, S_LEN / 128, BH_NUM);
    sgemm_nn_pv<<<gpv, blk>>>(P, V, attn);

    // --- O projection + residual x -> res1 ---
    sgemm_nt<<<gp, blk>>>(attn, E_DIM, 0, 0, Wo, E_DIM, 0, 0, res1, E_DIM, 0,
                          x, nullptr, N_TOK, E_DIM, E_DIM, 1, 1.f, 0);

    // --- LN1 -> h ---
    layernorm_rows<<<N_TOK, 256>>>(res1, g1, b1, h);

    // --- FFN1: relu(h @ W1^T + bb1) -> ffn ---
    dim3 gf1(F_DIM / 128, N_TOK / 128, 1);
    sgemm_nt<<<gf1, blk>>>(h, E_DIM, 0, 0, W1, E_DIM, 0, 0, ffn, F_DIM, 0,
                          nullptr, bb1, N_TOK, F_DIM, E_DIM, 1, 1.f, 1);

    // --- FFN2: ffn @ W2^T + bb2 + h -> res2 ---
    sgemm_nt<<<gp, blk>>>(ffn, F_DIM, 0, 0, W2, F_DIM, 0, 0, res2, E_DIM, 0,
                          h, bb2, N_TOK, E_DIM, F_DIM, 1, 1.f, 0);

    // --- LN2 -> out ---
    layernorm_rows<<<N_TOK, 256>>>(res2, g2, b2, out);
}

// round 4
// speedup vs baseline: 1.9322x; 1.9322x over previous
#include <cuda_runtime.h>
#include <cuda_bf16.h>
#include <math.h>
#include <stdint.h>

typedef __nv_bfloat16  bf16;
typedef __nv_bfloat162 bf162;

// ---------------------------------------------------------------------------
// Problem constants
// ---------------------------------------------------------------------------
#define E_DIM   1024
#define H_NUM   16
#define HD_DIM  64
#define F_DIM   4096
#define B_NUM   4
#define S_LEN   2048
#define N_TOK   (B_NUM * S_LEN)      // 8192
#define BH_NUM  (B_NUM * H_NUM)      // 64
#define LN_EPS  1e-5f

// ---------------------------------------------------------------------------
// Scratch buffers (static device globals) — total ~1.43 GB (< 2GB reloc limit)
// ---------------------------------------------------------------------------
// fp32
__device__ float g_P   [(size_t)BH_NUM * S_LEN * S_LEN];   // 1 GB; after softmax
                                                           // holds Ph/Pl (bf16)
                                                           // interleaved per row
__device__ float g_res1[(size_t)N_TOK * E_DIM];            // 32 MB (also V fp32)
__device__ float g_h   [(size_t)N_TOK * E_DIM];            // 32 MB
__device__ float g_res2[(size_t)N_TOK * E_DIM];            // 32 MB
// bf16 split pairs
__device__ bf16 g_xh [(size_t)N_TOK * E_DIM],  g_xl [(size_t)N_TOK * E_DIM];
__device__ bf16 g_Wqh[(size_t)E_DIM * E_DIM],  g_Wql[(size_t)E_DIM * E_DIM];
__device__ bf16 g_Wkh[(size_t)E_DIM * E_DIM],  g_Wkl[(size_t)E_DIM * E_DIM];
__device__ bf16 g_Wvh[(size_t)E_DIM * E_DIM],  g_Wvl[(size_t)E_DIM * E_DIM];
__device__ bf16 g_Woh[(size_t)E_DIM * E_DIM],  g_Wol[(size_t)E_DIM * E_DIM];
__device__ bf16 g_W1h[(size_t)F_DIM * E_DIM],  g_W1l[(size_t)F_DIM * E_DIM];
__device__ bf16 g_W2h[(size_t)E_DIM * F_DIM],  g_W2l[(size_t)E_DIM * F_DIM];
__device__ bf16 g_Qh [(size_t)N_TOK * E_DIM],  g_Ql [(size_t)N_TOK * E_DIM];
__device__ bf16 g_Kh [(size_t)N_TOK * E_DIM],  g_Kl [(size_t)N_TOK * E_DIM];
__device__ bf16 g_Vth[(size_t)BH_NUM * HD_DIM * S_LEN], g_Vtl[(size_t)BH_NUM * HD_DIM * S_LEN];
__device__ bf16 g_ah [(size_t)N_TOK * E_DIM],  g_al [(size_t)N_TOK * E_DIM];
__device__ bf16 g_hh [(size_t)N_TOK * E_DIM],  g_hl [(size_t)N_TOK * E_DIM];
__device__ bf16 g_fh [(size_t)N_TOK * F_DIM],  g_fl [(size_t)N_TOK * F_DIM];

// ---------------------------------------------------------------------------
// Helpers
// ---------------------------------------------------------------------------
__device__ __forceinline__ void split1(float v, bf16& h, bf16& l) {
    h = __float2bfloat16(v);
    l = __float2bfloat16(v - __bfloat162float(h));
}

__device__ __forceinline__ uint32_t smem_u32(const void* p) {
    return (uint32_t)__cvta_generic_to_shared(p);
}

__device__ __forceinline__ void ldsm4(uint32_t* r, uint32_t a) {
    asm volatile("ldmatrix.sync.aligned.m8n8.x4.shared.b16 {%0,%1,%2,%3}, [%4];"
        : "=r"(r[0]), "=r"(r[1]), "=r"(r[2]), "=r"(r[3]) : "r"(a));
}

__device__ __forceinline__ void mma16816(float* c, const uint32_t* a, const uint32_t* b) {
    asm volatile(
        "mma.sync.aligned.m16n8k16.row.col.f32.bf16.bf16.f32 "
        "{%0,%1,%2,%3}, {%4,%5,%6,%7}, {%8,%9}, {%0,%1,%2,%3};"
        : "+f"(c[0]), "+f"(c[1]), "+f"(c[2]), "+f"(c[3])
        : "r"(a[0]), "r"(a[1]), "r"(a[2]), "r"(a[3]), "r"(b[0]), "r"(b[1]));
}

__device__ __forceinline__ float blockReduceSum256(float v) {
    __shared__ float s[8];
    int lane = threadIdx.x & 31, wid = threadIdx.x >> 5;
    #pragma unroll
    for (int o = 16; o; o >>= 1) v += __shfl_xor_sync(0xffffffffu, v, o);
    __syncthreads();
    if (lane == 0) s[wid] = v;
    __syncthreads();
    float r = s[0];
    #pragma unroll
    for (int i = 1; i < 8; i++) r += s[i];
    return r;
}

__device__ __forceinline__ float blockReduceMax256(float v) {
    __shared__ float s[8];
    int lane = threadIdx.x & 31, wid = threadIdx.x >> 5;
    #pragma unroll
    for (int o = 16; o; o >>= 1) v = fmaxf(v, __shfl_xor_sync(0xffffffffu, v, o));
    __syncthreads();
    if (lane == 0) s[wid] = v;
    __syncthreads();
    float r = s[0];
    #pragma unroll
    for (int i = 1; i < 8; i++) r = fmaxf(r, s[i]);
    return r;
}

// ---------------------------------------------------------------------------
// bf16x3 tensor-core GEMM:  C = alpha * A @ B^T (+bias +relu +residual)
// A ~ Ahi+Alo [M,K] (row-major, K contiguous), B ~ Bhi+Blo [N,K].
// Batched over grid.z with (zb,zh) offsets; outputs fp32 and/or split bf16.
// BK=32, 256 threads = 8 warps.
// ---------------------------------------------------------------------------
#define GBK 32
#define GPAD 8

template<int BM, int BN, int WM, int WN>
__global__ __launch_bounds__(256, 1) void gemm_bf16x3(
    const bf16* __restrict__ Ahi, const bf16* __restrict__ Alo,
    int lda, long aOffB, long aOffH,
    const bf16* __restrict__ Bhi, const bf16* __restrict__ Blo,
    int ldb, long bOffB, long bOffH,
    float* Cf32, bf16* Chi, bf16* Clo,
    int ldc, long cOffB, long cOffH,
    const float* __restrict__ residual, const float* __restrict__ bias,
    int K, int nH, float alpha, int relu)
{
    constexpr int WARPS_N = BN / WN;
    constexpr int MF  = WM / 16;      // m16 frags per warp
    constexpr int NF  = WN / 8;       // n8  frags per warp
    constexpr int NG  = WN / 16;      // ldmatrix groups for B
    constexpr int LDS = GBK + GPAD;   // smem row stride (elems)
    constexpr int AIT = (BM * GBK) / (8 * 256);
    constexpr int BIT = (BN * GBK) / (8 * 256);

    __shared__ __align__(16) bf16 sAh[BM][LDS], sAl[BM][LDS];
    __shared__ __align__(16) bf16 sBh[BN][LDS], sBl[BN][LDS];

    const int tid  = threadIdx.x;
    const int warp = tid >> 5, lane = tid & 31;
    const int wr = warp / WARPS_N, wc = warp % WARPS_N;
    const int row0 = blockIdx.y * BM;
    const int col0 = blockIdx.x * BN;

    const int z  = blockIdx.z;
    const int zb = z / nH, zh = z % nH;
    const bf16* Ah = Ahi + (long)zb * aOffB + (long)zh * aOffH;
    const bf16* Al = Alo + (long)zb * aOffB + (long)zh * aOffH;
    const bf16* Bh = Bhi + (long)zb * bOffB + (long)zh * bOffH;
    const bf16* Bl = Blo + (long)zb * bOffB + (long)zh * bOffH;
    const long  zC = (long)zb * cOffB + (long)zh * cOffH;

    float acc[MF][NF][4];
    #pragma unroll
    for (int i = 0; i < MF; i++)
        #pragma unroll
        for (int j = 0; j < NF; j++)
            #pragma unroll
            for (int k = 0; k < 4; k++) acc[i][j][k] = 0.f;

    // ldmatrix lane addressing
    const int aRowL = ((lane >> 3) & 1) * 8 + (lane & 7);
    const int aColL = (lane >> 4) * 8;
    const int bRowL = (lane >> 4) * 8 + (lane & 7);
    const int bColL = ((lane >> 3) & 1) * 8;
    const uint32_t aBaseH = smem_u32(&sAh[wr * WM + aRowL][aColL]);
    const uint32_t aBaseL = smem_u32(&sAl[wr * WM + aRowL][aColL]);
    const uint32_t bBaseH = smem_u32(&sBh[wc * WN + bRowL][bColL]);
    const uint32_t bBaseL = smem_u32(&sBl[wc * WN + bRowL][bColL]);

    uint4 rah[AIT], ral[AIT], rbh[BIT], rbl[BIT];

    // prefetch tile 0
    #pragma unroll
    for (int i = 0; i < AIT; i++) {
        int idx = tid + i * 256, r = idx >> 2, c = (idx & 3) * 8;
        rah[i] = *(const uint4*)(Ah + (long)(row0 + r) * lda + c);
        ral[i] = *(const uint4*)(Al + (long)(row0 + r) * lda + c);
    }
    #pragma unroll
    for (int i = 0; i < BIT; i++) {
        int idx = tid + i * 256, r = idx >> 2, c = (idx & 3) * 8;
        rbh[i] = *(const uint4*)(Bh + (long)(col0 + r) * ldb + c);
        rbl[i] = *(const uint4*)(Bl + (long)(col0 + r) * ldb + c);
    }

    for (int k0 = 0; k0 < K; k0 += GBK) {
        __syncthreads();
        #pragma unroll
        for (int i = 0; i < AIT; i++) {
            int idx = tid + i * 256, r = idx >> 2, c = (idx & 3) * 8;
            *(uint4*)&sAh[r][c] = rah[i];
            *(uint4*)&sAl[r][c] = ral[i];
        }
        #pragma unroll
        for (int i = 0; i < BIT; i++) {
            int idx = tid + i * 256, r = idx >> 2, c = (idx & 3) * 8;
            *(uint4*)&sBh[r][c] = rbh[i];
            *(uint4*)&sBl[r][c] = rbl[i];
        }
        __syncthreads();

        if (k0 + GBK < K) {
            int kn = k0 + GBK;
            #pragma unroll
            for (int i = 0; i < AIT; i++) {
                int idx = tid + i * 256, r = idx >> 2, c = (idx & 3) * 8;
                rah[i] = *(const uint4*)(Ah + (long)(row0 + r) * lda + kn + c);
                ral[i] = *(const uint4*)(Al + (long)(row0 + r) * lda + kn + c);
            }
            #pragma unroll
            for (int i = 0; i < BIT; i++) {
                int idx = tid + i * 256, r = idx >> 2, c = (idx & 3) * 8;
                rbh[i] = *(const uint4*)(Bh + (long)(col0 + r) * ldb + kn + c);
                rbl[i] = *(const uint4*)(Bl + (long)(col0 + r) * ldb + kn + c);
            }
        }

        #pragma unroll
        for (int kk = 0; kk < 2; kk++) {
            const uint32_t koff = kk * 32;  // 16 elems * 2B
            uint32_t aH[MF][4], aL[MF][4];
            #pragma unroll
            for (int mi = 0; mi < MF; mi++) {
                ldsm4(aH[mi], aBaseH + mi * (16 * LDS * 2) + koff);
                ldsm4(aL[mi], aBaseL + mi * (16 * LDS * 2) + koff);
            }
            uint32_t bH[NF][2], bL[NF][2];
            #pragma unroll
            for (int gi = 0; gi < NG; gi++) {
                uint32_t t4[4];
                ldsm4(t4, bBaseH + gi * (16 * LDS * 2) + koff);
                bH[2 * gi][0] = t4[0]; bH[2 * gi][1] = t4[1];
                bH[2 * gi + 1][0] = t4[2]; bH[2 * gi + 1][1] = t4[3];
                ldsm4(t4, bBaseL + gi * (16 * LDS * 2) + koff);
                bL[2 * gi][0] = t4[0]; bL[2 * gi][1] = t4[1];
                bL[2 * gi + 1][0] = t4[2]; bL[2 * gi + 1][1] = t4[3];
            }
            #pragma unroll
            for (int mi = 0; mi < MF; mi++)
                #pragma unroll
                for (int nf = 0; nf < NF; nf++) {
                    mma16816(acc[mi][nf], aH[mi], bH[nf]);
                    mma16816(acc[mi][nf], aH[mi], bL[nf]);
                    mma16816(acc[mi][nf], aL[mi], bH[nf]);
                }
        }
    }

    // ---------------- epilogue ----------------
    float*       Cz = Cf32 ? Cf32 + zC : nullptr;
    bf16*        CH = Chi  ? Chi  + zC : nullptr;
    bf16*        CL = Clo  ? Clo  + zC : nullptr;
    const float* Rz = residual ? residual + zC : nullptr;

    #pragma unroll
    for (int mi = 0; mi < MF; mi++)
        #pragma unroll
        for (int nf = 0; nf < NF; nf++) {
            int rbase = row0 + wr * WM + mi * 16 + (lane >> 2);
            int c     = col0 + wc * WN + nf * 8 + (lane & 3) * 2;
            #pragma unroll
            for (int half = 0; half < 2; half++) {
                long r = rbase + half * 8;
                float v0 = acc[mi][nf][half * 2 + 0] * alpha;
                float v1 = acc[mi][nf][half * 2 + 1] * alpha;
                if (bias) { v0 += bias[c]; v1 += bias[c + 1]; }
                if (relu) { v0 = fmaxf(v0, 0.f); v1 = fmaxf(v1, 0.f); }
                if (Rz)   { v0 += Rz[r * (long)ldc + c]; v1 += Rz[r * (long)ldc + c + 1]; }
                if (Cz) {
                    float2 o = make_float2(v0, v1);
                    *(float2*)&Cz[r * (long)ldc + c] = o;
                }
                if (CH) {
                    bf16 h0, l0, h1, l1;
                    split1(v0, h0, l0);
                    split1(v1, h1, l1);
                    *(bf162*)&CH[r * (long)ldc + c] = __halves2bfloat162(h0, h1);
                    *(bf162*)&CL[r * (long)ldc + c] = __halves2bfloat162(l0, l1);
                }
            }
        }
}

// ---------------------------------------------------------------------------
// fp32 -> split bf16 conversion (4 elems/thread)
// ---------------------------------------------------------------------------
__global__ void split4(const float* __restrict__ in, bf16* __restrict__ hi,
                       bf16* __restrict__ lo, size_t n4)
{
    size_t i = (size_t)blockIdx.x * blockDim.x + threadIdx.x;
    if (i >= n4) return;
    float4 v = ((const float4*)in)[i];
    bf16 h0, l0, h1, l1, h2, l2, h3, l3;
    split1(v.x, h0, l0); split1(v.y, h1, l1);
    split1(v.z, h2, l2); split1(v.w, h3, l3);
    ((bf162*)hi)[2 * i + 0] = __halves2bfloat162(h0, h1);
    ((bf162*)hi)[2 * i + 1] = __halves2bfloat162(h2, h3);
    ((bf162*)lo)[2 * i + 0] = __halves2bfloat162(l0, l1);
    ((bf162*)lo)[2 * i + 1] = __halves2bfloat162(l2, l3);
}

// ---------------------------------------------------------------------------
// V [b,s,(h,d)] fp32 -> Vt [(b,h), d, s] split bf16
// ---------------------------------------------------------------------------
__global__ void transpose_split_v(const float* __restrict__ V,
                                  bf16* __restrict__ Vth, bf16* __restrict__ Vtl)
{
    __shared__ float t[32][33];
    int z = blockIdx.z, b = z >> 4, h = z & 15;
    int s0 = blockIdx.x * 32, d0 = blockIdx.y * 32;
    #pragma unroll
    for (int j = 0; j < 4; j++) {
        int s = s0 + threadIdx.y + j * 8;
        t[threadIdx.y + j * 8][threadIdx.x] =
            V[(size_t)(b * S_LEN + s) * E_DIM + h * HD_DIM + d0 + threadIdx.x];
    }
    __syncthreads();
    #pragma unroll
    for (int j = 0; j < 4; j++) {
        int d = d0 + threadIdx.y + j * 8;
        float v = t[threadIdx.x][threadIdx.y + j * 8];
        bf16 hh, ll;
        split1(v, hh, ll);
        size_t o = ((size_t)z * HD_DIM + d) * S_LEN + s0 + threadIdx.x;
        Vth[o] = hh;
        Vtl[o] = ll;
    }
}

// ---------------------------------------------------------------------------
// Softmax rows (S=2048). Reads fp32 row, writes split bf16 IN PLACE into the
// same buffer: hi at row*4096 (bf16 elems), lo at row*4096+2048.
// All reads complete before the first reduction's __syncthreads; writes after.
// ---------------------------------------------------------------------------
__global__ __launch_bounds__(256) void softmax_split_inplace(float* __restrict__ P)
{
    size_t row = blockIdx.x;
    const float4* p4 = (const float4*)(P + row * (size_t)S_LEN);
    int tid = threadIdx.x;

    float4 v0 = p4[2 * tid], v1 = p4[2 * tid + 1];
    float m = fmaxf(fmaxf(fmaxf(v0.x, v0.y), fmaxf(v0.z, v0.w)),
                    fmaxf(fmaxf(v1.x, v1.y), fmaxf(v1.z, v1.w)));
    m = blockReduceMax256(m);   // contains __syncthreads: all reads done after

    v0.x = __expf(v0.x - m); v0.y = __expf(v0.y - m);
    v0.z = __expf(v0.z - m); v0.w = __expf(v0.w - m);
    v1.x = __expf(v1.x - m); v1.y = __expf(v1.y - m);
    v1.z = __expf(v1.z - m); v1.w = __expf(v1.w - m);

    float s = (v0.x + v0.y + v0.z + v0.w) + (v1.x + v1.y + v1.z + v1.w);
    s = blockReduceSum256(s);
    float inv = 1.f / s;

    float vals[8] = {v0.x * inv, v0.y * inv, v0.z * inv, v0.w * inv,
                     v1.x * inv, v1.y * inv, v1.z * inv, v1.w * inv};

    bf16* rowb = (bf16*)P + row * (size_t)(2 * S_LEN);
    bf162* ph2 = (bf162*)rowb;                  // hi: 2048 bf16
    bf162* pl2 = (bf162*)(rowb + S_LEN);        // lo: 2048 bf16
    #pragma unroll
    for (int j = 0; j < 4; j++) {
        bf16 h0, l0, h1, l1;
        split1(vals[2 * j], h0, l0);
        split1(vals[2 * j + 1], h1, l1);
        ph2[4 * tid + j] = __halves2bfloat162(h0, h1);
        pl2[4 * tid + j] = __halves2bfloat162(l0, l1);
    }
}

// ---------------------------------------------------------------------------
// LayerNorm (E=1024), fp32 out + optional split bf16 out
// ---------------------------------------------------------------------------
__global__ __launch_bounds__(256) void layernorm_rows(
    const float* __restrict__ in,
    const float* __restrict__ g, const float* __restrict__ b,
    float* __restrict__ out, bf16* __restrict__ ohi, bf16* __restrict__ olo)
{
    size_t row = blockIdx.x;
    const float4* x4 = (const float4*)(in + row * E_DIM);
    float4 v = x4[threadIdx.x];

    float s  = v.x + v.y + v.z + v.w;
    float ss = v.x * v.x + v.y * v.y + v.z * v.z + v.w * v.w;
    s  = blockReduceSum256(s);
    ss = blockReduceSum256(ss);

    const float invE = 1.f / (float)E_DIM;
    float mu   = s * invE;
    float var  = ss * invE - mu * mu;
    float rstd = rsqrtf(var + LN_EPS);

    float4 gv = ((const float4*)g)[threadIdx.x];
    float4 bv = ((const float4*)b)[threadIdx.x];
    float4 o;
    o.x = (v.x - mu) * rstd * gv.x + bv.x;
    o.y = (v.y - mu) * rstd * gv.y + bv.y;
    o.z = (v.z - mu) * rstd * gv.z + bv.z;
    o.w = (v.w - mu) * rstd * gv.w + bv.w;
    ((float4*)(out + row * E_DIM))[threadIdx.x] = o;

    if (ohi) {
        bf16 h0, l0, h1, l1, h2, l2, h3, l3;
        split1(o.x, h0, l0); split1(o.y, h1, l1);
        split1(o.z, h2, l2); split1(o.w, h3, l3);
        bf162* ph = (bf162*)(ohi + row * E_DIM);
        bf162* pl = (bf162*)(olo + row * E_DIM);
        ph[2 * threadIdx.x + 0] = __halves2bfloat162(h0, h1);
        ph[2 * threadIdx.x + 1] = __halves2bfloat162(h2, h3);
        pl[2 * threadIdx.x + 0] = __halves2bfloat162(l0, l1);
        pl[2 * threadIdx.x + 1] = __halves2bfloat162(l2, l3);
    }
}

// ---------------------------------------------------------------------------
// Launch
// Inputs: 0:x 1:Wq 2:Wk 3:Wv 4:Wo 5:g1 6:b1 7:g2 8:b2 9:W1 10:bb1 11:W2 12:bb2
// ---------------------------------------------------------------------------
#define SYMADDR(v, s) cudaGetSymbolAddress((void**)&v, s)

extern "C" void kernel_launch(void* const* d_in, const int* in_sizes, int n_in,
                              void* d_out, int out_size)
{
    const float* x   = (const float*)d_in[0];
    const float* Wq  = (const float*)d_in[1];
    const float* Wk  = (const float*)d_in[2];
    const float* Wv  = (const float*)d_in[3];
    const float* Wo  = (const float*)d_in[4];
    const float* g1  = (const float*)d_in[5];
    const float* b1  = (const float*)d_in[6];
    const float* g2  = (const float*)d_in[7];
    const float* b2  = (const float*)d_in[8];
    const float* W1  = (const float*)d_in[9];
    const float* bb1 = (const float*)d_in[10];
    const float* W2  = (const float*)d_in[11];
    const float* bb2 = (const float*)d_in[12];
    float* out = (float*)d_out;

    float *P, *res1, *h, *res2;
    bf16 *xh, *xl, *Wqh, *Wql, *Wkh, *Wkl, *Wvh, *Wvl, *Woh, *Wol;
    bf16 *W1h, *W1l, *W2h, *W2l, *Qh, *Ql, *Kh, *Kl, *Vth, *Vtl;
    bf16 *ah, *al, *hh, *hl, *fh, *fl;
    SYMADDR(P, g_P); SYMADDR(res1, g_res1);
    SYMADDR(h, g_h); SYMADDR(res2, g_res2);
    SYMADDR(xh, g_xh); SYMADDR(xl, g_xl);
    SYMADDR(Wqh, g_Wqh); SYMADDR(Wql, g_Wql);
    SYMADDR(Wkh, g_Wkh); SYMADDR(Wkl, g_Wkl);
    SYMADDR(Wvh, g_Wvh); SYMADDR(Wvl, g_Wvl);
    SYMADDR(Woh, g_Woh); SYMADDR(Wol, g_Wol);
    SYMADDR(W1h, g_W1h); SYMADDR(W1l, g_W1l);
    SYMADDR(W2h, g_W2h); SYMADDR(W2l, g_W2l);
    SYMADDR(Qh, g_Qh); SYMADDR(Ql, g_Ql);
    SYMADDR(Kh, g_Kh); SYMADDR(Kl, g_Kl);
    SYMADDR(Vth, g_Vth); SYMADDR(Vtl, g_Vtl);
    SYMADDR(ah, g_ah); SYMADDR(al, g_al);
    SYMADDR(hh, g_hh); SYMADDR(hl, g_hl);
    SYMADDR(fh, g_fh); SYMADDR(fl, g_fl);

    float* Vf32 = res1;                 // V projection parks in res1 (free here)
    bf16*  Pb16 = (bf16*)P;             // after softmax: hi/lo interleaved rows

    dim3 blk(256);

    // --- split inputs/weights ---
    auto splitLaunch = [&](const float* src, bf16* hi, bf16* lo, size_t n) {
        size_t n4 = n / 4;
        split4<<<(unsigned)((n4 + 255) / 256), 256>>>(src, hi, lo, n4);
    };
    splitLaunch(x,  xh,  xl,  (size_t)N_TOK * E_DIM);
    splitLaunch(Wq, Wqh, Wql, (size_t)E_DIM * E_DIM);
    splitLaunch(Wk, Wkh, Wkl, (size_t)E_DIM * E_DIM);
    splitLaunch(Wv, Wvh, Wvl, (size_t)E_DIM * E_DIM);
    splitLaunch(Wo, Woh, Wol, (size_t)E_DIM * E_DIM);
    splitLaunch(W1, W1h, W1l, (size_t)F_DIM * E_DIM);
    splitLaunch(W2, W2h, W2l, (size_t)E_DIM * F_DIM);

    // --- QKV projections ---
    dim3 gp(E_DIM / 128, N_TOK / 128, 1);
    gemm_bf16x3<128,128,64,32><<<gp, blk>>>(
        xh, xl, E_DIM, 0, 0,  Wqh, Wql, E_DIM, 0, 0,
        nullptr, Qh, Ql, E_DIM, 0, 0,
        nullptr, nullptr, E_DIM, 1, 1.f, 0);
    gemm_bf16x3<128,128,64,32><<<gp, blk>>>(
        xh, xl, E_DIM, 0, 0,  Wkh, Wkl, E_DIM, 0, 0,
        nullptr, Kh, Kl, E_DIM, 0, 0,
        nullptr, nullptr, E_DIM, 1, 1.f, 0);
    gemm_bf16x3<128,128,64,32><<<gp, blk>>>(
        xh, xl, E_DIM, 0, 0,  Wvh, Wvl, E_DIM, 0, 0,
        Vf32, nullptr, nullptr, E_DIM, 0, 0,
        nullptr, nullptr, E_DIM, 1, 1.f, 0);

    // --- V transpose + split ---
    transpose_split_v<<<dim3(S_LEN / 32, HD_DIM / 32, BH_NUM), dim3(32, 8)>>>(Vf32, Vth, Vtl);

    // --- scores = QK^T / 8 ---
    dim3 gs(S_LEN / 128, S_LEN / 128, BH_NUM);
    gemm_bf16x3<128,128,64,32><<<gs, blk>>>(
        Qh, Ql, E_DIM, (long)S_LEN * E_DIM, HD_DIM,
        Kh, Kl, E_DIM, (long)S_LEN * E_DIM, HD_DIM,
        P, nullptr, nullptr, S_LEN, (long)H_NUM * S_LEN * S_LEN, (long)S_LEN * S_LEN,
        nullptr, nullptr, HD_DIM, H_NUM, 0.125f, 0);

    // --- softmax -> split probs in place (row stride 4096 bf16) ---
    softmax_split_inplace<<<BH_NUM * S_LEN, 256>>>(P);

    // --- attn = P @ V (via Vt), written to [b,s,(h,d)] split ---
    dim3 gpv(1, S_LEN / 128, BH_NUM);
    gemm_bf16x3<128,64,32,32><<<gpv, blk>>>(
        Pb16, Pb16 + S_LEN,                       // hi rows / lo rows
        2 * S_LEN,                                // lda = 4096 bf16
        (long)H_NUM * S_LEN * 2 * S_LEN, (long)S_LEN * 2 * S_LEN,
        Vth, Vtl, S_LEN, (long)H_NUM * HD_DIM * S_LEN, (long)HD_DIM * S_LEN,
        nullptr, ah, al, E_DIM, (long)S_LEN * E_DIM, HD_DIM,
        nullptr, nullptr, S_LEN, H_NUM, 1.f, 0);

    // --- O projection + residual x ---
    gemm_bf16x3<128,128,64,32><<<gp, blk>>>(
        ah, al, E_DIM, 0, 0,  Woh, Wol, E_DIM, 0, 0,
        res1, nullptr, nullptr, E_DIM, 0, 0,
        x, nullptr, E_DIM, 1, 1.f, 0);

    // --- LN1 -> h (fp32 + split) ---
    layernorm_rows<<<N_TOK, 256>>>(res1, g1, b1, h, hh, hl);

    // --- FFN1: relu(h @ W1^T + bb1) -> split ---
    dim3 gf1(F_DIM / 128, N_TOK / 128, 1);
    gemm_bf16x3<128,128,64,32><<<gf1, blk>>>(
        hh, hl, E_DIM, 0, 0,  W1h, W1l, E_DIM, 0, 0,
        nullptr, fh, fl, F_DIM, 0, 0,
        nullptr, bb1, E_DIM, 1, 1.f, 1);

    // --- FFN2: ffn @ W2^T + bb2 + h ---
    gemm_bf16x3<128,128,64,32><<<gp, blk>>>(
        fh, fl, F_DIM, 0, 0,  W2h, W2l, F_DIM, 0, 0,
        res2, nullptr, nullptr, E_DIM, 0, 0,
        h, bb2, F_DIM, 1, 1.f, 0);

    // --- LN2 -> out ---
    layernorm_rows<<<N_TOK, 256>>>(res2, g2, b2, out, nullptr, nullptr);
}